// round 3
// baseline (speedup 1.0000x reference)
#include <cuda_runtime.h>
#include <cstdint>

#define MDIM 16384
#define NDIM 4096
#define KDIM 4096
#define BM 128
#define BN 256
#define BK 32
#define NKT (KDIM / BK)           // 128
#define ASTRIDE 36                // floats per padded row
#define A_FLOATS (BM * ASTRIDE)   // 4608
#define B_FLOATS (BN * ASTRIDE)   // 9216
#define STAGE_FLOATS (A_FLOATS + B_FLOATS)          // 13824
#define SMEM_BYTES (3 * STAGE_FLOATS * 4)           // 165888
#define NTHR 256

__device__ float g_xtf[(size_t)MDIM * KDIM];   // tf32-rounded x
__device__ float g_weff[(size_t)NDIM * KDIM];  // tf32-rounded (W + 2*B@A)

// ---------------- helpers ----------------
__device__ __forceinline__ uint32_t smem_u32(const void* p) {
    uint32_t a;
    asm("{ .reg .u64 t; cvta.to.shared.u64 t, %1; cvt.u32.u64 %0, t; }" : "=r"(a) : "l"(p));
    return a;
}
__device__ __forceinline__ float rna_tf32(float f) {
    uint32_t u;
    asm("cvt.rna.tf32.f32 %0, %1;" : "=r"(u) : "f"(f));
    return __uint_as_float(u);
}
__device__ __forceinline__ void cp_async16(uint32_t saddr, const void* gptr) {
    asm volatile("cp.async.cg.shared.global [%0], [%1], 16;"
                 :: "r"(saddr), "l"(__cvta_generic_to_global(gptr)) : "memory");
}
#define CP_COMMIT() asm volatile("cp.async.commit_group;" ::: "memory")
#define CP_WAIT1()  asm volatile("cp.async.wait_group 1;" ::: "memory")

__device__ __forceinline__ void mma_tf32(float c[4], uint32_t a0, uint32_t a1,
                                         uint32_t a2, uint32_t a3,
                                         uint32_t b0, uint32_t b1) {
    asm volatile(
        "mma.sync.aligned.m16n8k8.row.col.f32.tf32.tf32.f32 "
        "{%0,%1,%2,%3}, {%4,%5,%6,%7}, {%8,%9}, {%0,%1,%2,%3};"
        : "+f"(c[0]), "+f"(c[1]), "+f"(c[2]), "+f"(c[3])
        : "r"(a0), "r"(a1), "r"(a2), "r"(a3), "r"(b0), "r"(b1));
}

// ---------------- prep: round x to tf32 ----------------
__global__ void round_x_kernel(const float* __restrict__ x) {
    size_t n4 = (size_t)MDIM * KDIM / 4;
    size_t stride = (size_t)gridDim.x * blockDim.x;
    const float4* in = (const float4*)x;
    float4* outp = (float4*)g_xtf;
    for (size_t i = blockIdx.x * (size_t)blockDim.x + threadIdx.x; i < n4; i += stride) {
        float4 v = in[i];
        v.x = rna_tf32(v.x); v.y = rna_tf32(v.y);
        v.z = rna_tf32(v.z); v.w = rna_tf32(v.w);
        outp[i] = v;
    }
}

// ---------------- prep: Weff = tf32(W + 2 * lora_B @ lora_A) ----------------
__global__ void lora_prep_kernel(const float* __restrict__ w, const float* __restrict__ lA,
                                 const float* __restrict__ lB) {
    int tid = threadIdx.x;
    int grp = tid >> 6, lane = tid & 63;
    int o = blockIdx.x * 4 + grp;
    float bv[16];
#pragma unroll
    for (int r = 0; r < 16; r++) bv[r] = lB[o * 16 + r] * 2.0f;
    const float4* wr = (const float4*)(w + (size_t)o * KDIM);
    float4* er = (float4*)(g_weff + (size_t)o * KDIM);
#pragma unroll 4
    for (int i = 0; i < 16; i++) {
        int j = lane + i * 64;
        float4 acc = wr[j];
#pragma unroll
        for (int r = 0; r < 16; r++) {
            float4 a = ((const float4*)(lA + (size_t)r * KDIM))[j];
            acc.x += bv[r] * a.x; acc.y += bv[r] * a.y;
            acc.z += bv[r] * a.z; acc.w += bv[r] * a.w;
        }
        acc.x = rna_tf32(acc.x); acc.y = rna_tf32(acc.y);
        acc.z = rna_tf32(acc.z); acc.w = rna_tf32(acc.w);
        er[j] = acc;
    }
}

// ---------------- main GEMM ----------------
__global__ __launch_bounds__(NTHR, 1)
void lora_gemm_kernel(const float* __restrict__ bias, float* __restrict__ out) {
    extern __shared__ float smem[];
    const int tid = threadIdx.x;
    const int wid = tid >> 5, lane = tid & 31;
    const int wm = wid >> 2, wn = wid & 3;            // 2 x 4 warp grid
    const int m0 = blockIdx.x * BM, n0 = blockIdx.y * BN;

    const uint32_t sbase = smem_u32(smem);
    const int arow = tid >> 3, ac4 = tid & 7;         // producer decomposition

    // issue cp.async for one stage
    auto issue = [&](int s, int kt) {
        uint32_t sA = sbase + s * (STAGE_FLOATS * 4);
        uint32_t sB = sA + A_FLOATS * 4;
        const float* gA = g_xtf + (size_t)(m0 + arow) * KDIM + kt * BK + ac4 * 4;
        const float* gB = g_weff + (size_t)(n0 + arow) * KDIM + kt * BK + ac4 * 4;
#pragma unroll
        for (int i = 0; i < 4; i++)   // A: 128 rows x 8 chunks = 1024; 256 thr x 4
            cp_async16(sA + (arow + i * 32) * (ASTRIDE * 4) + ac4 * 16,
                       gA + (size_t)(i * 32) * KDIM);
#pragma unroll
        for (int i = 0; i < 8; i++)   // B: 256 rows x 8 chunks = 2048; 256 thr x 8
            cp_async16(sB + (arow + i * 32) * (ASTRIDE * 4) + ac4 * 16,
                       gB + (size_t)(i * 32) * KDIM);
    };

    float acc[4][8][4];
#pragma unroll
    for (int ma = 0; ma < 4; ma++)
#pragma unroll
        for (int na = 0; na < 8; na++)
#pragma unroll
            for (int j = 0; j < 4; j++) acc[ma][na][j] = 0.0f;

    issue(0, 0); CP_COMMIT();
    issue(1, 1); CP_COMMIT();

    const int g = lane >> 2, t = lane & 3;
    for (int kt = 0; kt < NKT; ++kt) {
        int s = kt - (kt / 3) * 3;
        CP_WAIT1();
        __syncthreads();
        if (kt + 2 < NKT) {
            int s2 = (kt + 2) - ((kt + 2) / 3) * 3;
            issue(s2, kt + 2);
        }
        CP_COMMIT();

        const float* As = smem + s * STAGE_FLOATS;
        const float* Bs = As + A_FLOATS;
        const uint32_t* pa = (const uint32_t*)(As + (wm * 64 + g) * ASTRIDE + t);
        const uint32_t* pb = (const uint32_t*)(Bs + (wn * 64 + g) * ASTRIDE + t);
#pragma unroll
        for (int ks = 0; ks < 4; ks++) {
            uint32_t af[4][4], bf[8][2];
#pragma unroll
            for (int ma = 0; ma < 4; ma++) {
                int o = ma * (16 * ASTRIDE) + ks * 8;
                af[ma][0] = pa[o];
                af[ma][1] = pa[o + 8 * ASTRIDE];
                af[ma][2] = pa[o + 4];
                af[ma][3] = pa[o + 8 * ASTRIDE + 4];
            }
#pragma unroll
            for (int na = 0; na < 8; na++) {
                int o = na * (8 * ASTRIDE) + ks * 8;
                bf[na][0] = pb[o];
                bf[na][1] = pb[o + 4];
            }
#pragma unroll
            for (int ma = 0; ma < 4; ma++)
#pragma unroll
                for (int na = 0; na < 8; na++)
                    mma_tf32(acc[ma][na], af[ma][0], af[ma][1], af[ma][2], af[ma][3],
                             bf[na][0], bf[na][1]);
        }
        __syncthreads();
    }

    // epilogue: fused bias + coalesced float2 stores
    const int r0 = m0 + wm * 64 + g;
    const int cbase = n0 + wn * 64 + t * 2;
    float2 bv[8];
#pragma unroll
    for (int na = 0; na < 8; na++)
        bv[na] = *(const float2*)(bias + cbase + na * 8);
#pragma unroll
    for (int ma = 0; ma < 4; ma++) {
        size_t row = (size_t)(r0 + ma * 16);
#pragma unroll
        for (int na = 0; na < 8; na++) {
            float2 v0 = make_float2(acc[ma][na][0] + bv[na].x, acc[ma][na][1] + bv[na].y);
            float2 v1 = make_float2(acc[ma][na][2] + bv[na].x, acc[ma][na][3] + bv[na].y);
            *(float2*)(out + row * NDIM + cbase + na * 8) = v0;
            *(float2*)(out + (row + 8) * NDIM + cbase + na * 8) = v1;
        }
    }
}

// ---------------- launch ----------------
extern "C" void kernel_launch(void* const* d_in, const int* in_sizes, int n_in,
                              void* d_out, int out_size) {
    const float* x      = (const float*)d_in[0];
    const float* weight = (const float*)d_in[1];
    const float* bias   = (const float*)d_in[2];
    const float* lora_A = (const float*)d_in[3];
    const float* lora_B = (const float*)d_in[4];
    float* out = (float*)d_out;

    cudaFuncSetAttribute(lora_gemm_kernel, cudaFuncAttributeMaxDynamicSharedMemorySize,
                         SMEM_BYTES);

    round_x_kernel<<<8192, 256>>>(x);
    lora_prep_kernel<<<NDIM / 4, 256>>>(weight, lora_A, lora_B);
    dim3 grid(MDIM / BM, NDIM / BN);
    lora_gemm_kernel<<<grid, NTHR, SMEM_BYTES>>>(bias, out);
}

// round 4
// speedup vs baseline: 1.0005x; 1.0005x over previous
#include <cuda_runtime.h>
#include <cstdint>

#define MDIM 16384
#define NDIM 4096
#define KDIM 4096
#define BM 128
#define BN 256
#define BK 32
#define NKT (KDIM / BK)           // 128
#define ASTRIDE 36                // floats per padded row
#define A_FLOATS (BM * ASTRIDE)   // 4608
#define B_FLOATS (BN * ASTRIDE)   // 9216
#define STAGE_FLOATS (A_FLOATS + B_FLOATS)          // 13824
#define SMEM_BYTES (3 * STAGE_FLOATS * 4)           // 165888
#define NTHR 256

__device__ float g_xtf[(size_t)MDIM * KDIM];   // tf32-rounded x
__device__ float g_weff[(size_t)NDIM * KDIM];  // tf32-rounded (W + 2*B@A)

// ---------------- helpers ----------------
__device__ __forceinline__ uint32_t smem_u32(const void* p) {
    uint32_t a;
    asm("{ .reg .u64 t; cvta.to.shared.u64 t, %1; cvt.u32.u64 %0, t; }" : "=r"(a) : "l"(p));
    return a;
}
__device__ __forceinline__ float rna_tf32(float f) {
    uint32_t u;
    asm("cvt.rna.tf32.f32 %0, %1;" : "=r"(u) : "f"(f));
    return __uint_as_float(u);
}
__device__ __forceinline__ void cp_async16(uint32_t saddr, const void* gptr) {
    asm volatile("cp.async.cg.shared.global [%0], [%1], 16;"
                 :: "r"(saddr), "l"(__cvta_generic_to_global(gptr)) : "memory");
}
#define CP_COMMIT() asm volatile("cp.async.commit_group;" ::: "memory")
#define CP_WAIT1()  asm volatile("cp.async.wait_group 1;" ::: "memory")
#define CP_WAIT0()  asm volatile("cp.async.wait_group 0;" ::: "memory")

__device__ __forceinline__ void mma_tf32(float c[4], uint32_t a0, uint32_t a1,
                                         uint32_t a2, uint32_t a3,
                                         uint32_t b0, uint32_t b1) {
    asm volatile(
        "mma.sync.aligned.m16n8k8.row.col.f32.tf32.tf32.f32 "
        "{%0,%1,%2,%3}, {%4,%5,%6,%7}, {%8,%9}, {%0,%1,%2,%3};"
        : "+f"(c[0]), "+f"(c[1]), "+f"(c[2]), "+f"(c[3])
        : "r"(a0), "r"(a1), "r"(a2), "r"(a3), "r"(b0), "r"(b1));
}

// ---------------- prep: round x to tf32 ----------------
__global__ void round_x_kernel(const float* __restrict__ x) {
    size_t n4 = (size_t)MDIM * KDIM / 4;
    size_t stride = (size_t)gridDim.x * blockDim.x;
    const float4* in = (const float4*)x;
    float4* outp = (float4*)g_xtf;
    for (size_t i = blockIdx.x * (size_t)blockDim.x + threadIdx.x; i < n4; i += stride) {
        float4 v = in[i];
        v.x = rna_tf32(v.x); v.y = rna_tf32(v.y);
        v.z = rna_tf32(v.z); v.w = rna_tf32(v.w);
        outp[i] = v;
    }
}

// ---------------- prep: Weff = tf32(W + 2 * lora_B @ lora_A) ----------------
__global__ void lora_prep_kernel(const float* __restrict__ w, const float* __restrict__ lA,
                                 const float* __restrict__ lB) {
    int tid = threadIdx.x;
    int grp = tid >> 6, lane = tid & 63;
    int o = blockIdx.x * 4 + grp;
    float bv[16];
#pragma unroll
    for (int r = 0; r < 16; r++) bv[r] = lB[o * 16 + r] * 2.0f;
    const float4* wr = (const float4*)(w + (size_t)o * KDIM);
    float4* er = (float4*)(g_weff + (size_t)o * KDIM);
#pragma unroll 4
    for (int i = 0; i < 16; i++) {
        int j = lane + i * 64;
        float4 acc = wr[j];
#pragma unroll
        for (int r = 0; r < 16; r++) {
            float4 a = ((const float4*)(lA + (size_t)r * KDIM))[j];
            acc.x += bv[r] * a.x; acc.y += bv[r] * a.y;
            acc.z += bv[r] * a.z; acc.w += bv[r] * a.w;
        }
        acc.x = rna_tf32(acc.x); acc.y = rna_tf32(acc.y);
        acc.z = rna_tf32(acc.z); acc.w = rna_tf32(acc.w);
        er[j] = acc;
    }
}

// ---------------- main GEMM ----------------
__global__ __launch_bounds__(NTHR, 1)
void lora_gemm_kernel(const float* __restrict__ bias, float* __restrict__ out) {
    extern __shared__ float smem[];
    const int tid = threadIdx.x;
    const int wid = tid >> 5, lane = tid & 31;
    const int wm = wid >> 2, wn = wid & 3;            // 2 x 4 warp grid
    const int m0 = blockIdx.x * BM, n0 = blockIdx.y * BN;

    const uint32_t sbase = smem_u32(smem);
    const int arow = tid >> 3, ac4 = tid & 7;         // producer decomposition

    auto issue = [&](int s, int kt) {
        uint32_t sA = sbase + s * (STAGE_FLOATS * 4);
        uint32_t sB = sA + A_FLOATS * 4;
        const float* gA = g_xtf + (size_t)(m0 + arow) * KDIM + kt * BK + ac4 * 4;
        const float* gB = g_weff + (size_t)(n0 + arow) * KDIM + kt * BK + ac4 * 4;
#pragma unroll
        for (int i = 0; i < 4; i++)
            cp_async16(sA + (arow + i * 32) * (ASTRIDE * 4) + ac4 * 16,
                       gA + (size_t)(i * 32) * KDIM);
#pragma unroll
        for (int i = 0; i < 8; i++)
            cp_async16(sB + (arow + i * 32) * (ASTRIDE * 4) + ac4 * 16,
                       gB + (size_t)(i * 32) * KDIM);
    };

    float acc[4][8][4];
#pragma unroll
    for (int ma = 0; ma < 4; ma++)
#pragma unroll
        for (int na = 0; na < 8; na++)
#pragma unroll
            for (int j = 0; j < 4; j++) acc[ma][na][j] = 0.0f;

    issue(0, 0); CP_COMMIT();
    issue(1, 1); CP_COMMIT();

    const int g = lane >> 2, t = lane & 3;
    uint32_t af[2][4][4], bf[2][8][2];

    for (int kt = 0; kt < NKT; ++kt) {
        int s = kt - (kt / 3) * 3;
        if (kt + 2 < NKT) { CP_WAIT1(); } else { CP_WAIT0(); }
        __syncthreads();
        if (kt + 2 < NKT) {
            int s2 = (kt + 2) - ((kt + 2) / 3) * 3;
            issue(s2, kt + 2);
            CP_COMMIT();
        }

        const float* As = smem + s * STAGE_FLOATS;
        const float* Bs = As + A_FLOATS;
        const uint32_t* pa = (const uint32_t*)(As + (wm * 64 + g) * ASTRIDE + t);
        const uint32_t* pb = (const uint32_t*)(Bs + (wn * 64 + g) * ASTRIDE + t);

        // load frags for ks=0
#pragma unroll
        for (int ma = 0; ma < 4; ma++) {
            int o = ma * (16 * ASTRIDE);
            af[0][ma][0] = pa[o];
            af[0][ma][1] = pa[o + 8 * ASTRIDE];
            af[0][ma][2] = pa[o + 4];
            af[0][ma][3] = pa[o + 8 * ASTRIDE + 4];
        }
#pragma unroll
        for (int na = 0; na < 8; na++) {
            int o = na * (8 * ASTRIDE);
            bf[0][na][0] = pb[o];
            bf[0][na][1] = pb[o + 4];
        }

#pragma unroll
        for (int ks = 0; ks < 4; ks++) {
            int cur = ks & 1;
            if (ks < 3) {
                int nxt = cur ^ 1, o0 = (ks + 1) * 8;
#pragma unroll
                for (int ma = 0; ma < 4; ma++) {
                    int o = ma * (16 * ASTRIDE) + o0;
                    af[nxt][ma][0] = pa[o];
                    af[nxt][ma][1] = pa[o + 8 * ASTRIDE];
                    af[nxt][ma][2] = pa[o + 4];
                    af[nxt][ma][3] = pa[o + 8 * ASTRIDE + 4];
                }
#pragma unroll
                for (int na = 0; na < 8; na++) {
                    int o = na * (8 * ASTRIDE) + o0;
                    bf[nxt][na][0] = pb[o];
                    bf[nxt][na][1] = pb[o + 4];
                }
            }
#pragma unroll
            for (int ma = 0; ma < 4; ma++)
#pragma unroll
                for (int na = 0; na < 8; na++)
                    mma_tf32(acc[ma][na], af[cur][ma][0], af[cur][ma][1],
                             af[cur][ma][2], af[cur][ma][3],
                             bf[cur][na][0], bf[cur][na][1]);
        }
    }

    // epilogue: fused bias + coalesced float2 stores
    const int r0 = m0 + wm * 64 + g;
    const int cbase = n0 + wn * 64 + t * 2;
    float2 bv[8];
#pragma unroll
    for (int na = 0; na < 8; na++)
        bv[na] = *(const float2*)(bias + cbase + na * 8);
#pragma unroll
    for (int ma = 0; ma < 4; ma++) {
        size_t row = (size_t)(r0 + ma * 16);
#pragma unroll
        for (int na = 0; na < 8; na++) {
            float2 v0 = make_float2(acc[ma][na][0] + bv[na].x, acc[ma][na][1] + bv[na].y);
            float2 v1 = make_float2(acc[ma][na][2] + bv[na].x, acc[ma][na][3] + bv[na].y);
            *(float2*)(out + row * NDIM + cbase + na * 8) = v0;
            *(float2*)(out + (row + 8) * NDIM + cbase + na * 8) = v1;
        }
    }
}

// ---------------- launch ----------------
extern "C" void kernel_launch(void* const* d_in, const int* in_sizes, int n_in,
                              void* d_out, int out_size) {
    const float* x      = (const float*)d_in[0];
    const float* weight = (const float*)d_in[1];
    const float* bias   = (const float*)d_in[2];
    const float* lora_A = (const float*)d_in[3];
    const float* lora_B = (const float*)d_in[4];
    float* out = (float*)d_out;

    cudaFuncSetAttribute(lora_gemm_kernel, cudaFuncAttributeMaxDynamicSharedMemorySize,
                         SMEM_BYTES);

    round_x_kernel<<<8192, 256>>>(x);
    lora_prep_kernel<<<NDIM / 4, 256>>>(weight, lora_A, lora_B);
    dim3 grid(MDIM / BM, NDIM / BN);
    lora_gemm_kernel<<<grid, NTHR, SMEM_BYTES>>>(bias, out);
}